// round 9
// baseline (speedup 1.0000x reference)
#include <cuda_runtime.h>
#include <math.h>
#include <stdint.h>

#define D_IN   768
#define TWO_D  1536
#define Q_N    128
#define S_N    512
#define C_N    64
#define JCHUNKS 8
#define JPER   (TWO_D / JCHUNKS)    /* 192 */

typedef unsigned long long ull;

// Scratch (device globals: allocation-free per harness rules)
__device__ float    v9_hq[Q_N * TWO_D];             // hq (+b1)  [128,1536]
__device__ float    v9_hs[S_N * TWO_D];             // hs        [512,1536]
__device__ double   v9_part[JCHUNKS * Q_N * S_N];   // fp64 partial scores per j-chunk
__device__ double   v9_loss[Q_N];
__device__ unsigned v9_ticket = 0;

// fp32 -> tf32 RNA rounding (matches cuBLAS TF32 input quantization = reference)
__device__ __forceinline__ float v9_tf32(float x) {
    unsigned u;
    asm("cvt.rna.tf32.f32 %0, %1;" : "=r"(u) : "f"(x));
    return __uint_as_float(u);
}

// m16n8k8 tf32 mma (base ISA, sm_80+)
__device__ __forceinline__ void v9_mma(float d[4], const unsigned a[4], const unsigned b[2]) {
    asm volatile(
        "mma.sync.aligned.m16n8k8.row.col.f32.tf32.tf32.f32 "
        "{%0,%1,%2,%3}, {%4,%5,%6,%7}, {%8,%9}, {%0,%1,%2,%3};"
        : "+f"(d[0]), "+f"(d[1]), "+f"(d[2]), "+f"(d[3])
        : "r"(a[0]), "r"(a[1]), "r"(a[2]), "r"(a[3]), "r"(b[0]), "r"(b[1]));
}

// packed f32x2 (base ISA on sm_100+ family; SASS FADD2/FFMA2)
#define V9_ADD2(d, a, b) \
    asm("add.rn.f32x2 %0, %1, %2;" : "=l"(d) : "l"(a), "l"(b))
#define V9_FMA2(acc, t, w) \
    asm("fma.rn.f32x2 %0, %1, %2, %0;" : "+l"(acc) : "l"(t), "l"(w))

// packed relu on the ALU pipe (IMAX): valid for all non-NaN floats
__device__ __forceinline__ ull v9_relu2(ull t) {
    unsigned lo, hi;
    asm("mov.b64 {%0,%1}, %2;" : "=r"(lo), "=r"(hi) : "l"(t));
    int l2 = max((int)lo, 0);
    int h2 = max((int)hi, 0);
    ull r;
    asm("mov.b64 %0, {%1,%2};" : "=l"(r) : "r"((unsigned)l2), "r"((unsigned)h2));
    return r;
}

// ---------------------------------------------------------------------------
// TF32 tensor-core GEMM, single-K: h = tf32(A) @ tf32(W1 slice).T (+b1 on query)
// CTA 64m x 64n, 128 threads = 4 warps (2M x 2N), warp tile 32x32.
// K=768 in 24 double-buffered k-tiles of 32, ONE barrier per iter.
// grid = (24, 10), occupancy 4 (4 warps/SMSP latency hiding).
// ---------------------------------------------------------------------------
#define V9_ST     40
#define V9_ASZ    (2 * 64 * V9_ST)
#define V9_BSZ    (2 * 64 * V9_ST)
#define V9_SMEM   ((V9_ASZ + V9_BSZ) * 4)     /* 40960 B */

__global__ void __launch_bounds__(128, 4)
v9_gemm(const float* __restrict__ query,
        const float* __restrict__ support,
        const float* __restrict__ W1,
        const float* __restrict__ b1)
{
    extern __shared__ __align__(16) float smem[];
    float* As = smem;              // [2][64][40]
    float* Bs = smem + V9_ASZ;     // [2][64][40]

    const int tid  = threadIdx.x;
    const int lane = tid & 31;
    const int wid  = tid >> 5;
    const int warpM = wid & 1;          // 0..1
    const int warpN = wid >> 1;         // 0..1
    const int g = lane >> 2;            // 0..7
    const int t = lane & 3;             // 0..3

    const bool isQ  = (blockIdx.y < 2);
    const float* Arow = isQ ? (query + (size_t)blockIdx.y * 64 * D_IN)
                            : (support + (size_t)(blockIdx.y - 2) * 64 * D_IN);
    const int   wOff  = isQ ? 0 : D_IN;
    const int   jBase = blockIdx.x * 64;
    float* Crow = isQ ? (v9_hq + (size_t)blockIdx.y * 64 * TWO_D)
                      : (v9_hs + (size_t)(blockIdx.y - 2) * 64 * TWO_D);

    // staging: 64 rows x 32 k per tile; 2 threads/row, 16 k (2 8-k groups) each
    const int st_row = tid >> 1;            // 0..63
    const int st_k16 = (tid & 1) * 16;      // 0 or 16
    const float* aSeg = Arow + (size_t)st_row * D_IN + st_k16;
    const float* bSeg = W1 + (size_t)(jBase + st_row) * TWO_D + wOff + st_k16;

    float4 pa[4], pb[4];   // [group*2 + half]: groups at k16+0, k16+8
    #define V9_PREFETCH(kb) do {                                    \
        pa[0] = *(const float4*)(aSeg + (kb));                      \
        pa[1] = *(const float4*)(aSeg + (kb) + 4);                  \
        pa[2] = *(const float4*)(aSeg + (kb) + 8);                  \
        pa[3] = *(const float4*)(aSeg + (kb) + 12);                 \
        pb[0] = *(const float4*)(bSeg + (kb));                      \
        pb[1] = *(const float4*)(bSeg + (kb) + 4);                  \
        pb[2] = *(const float4*)(bSeg + (kb) + 8);                  \
        pb[3] = *(const float4*)(bSeg + (kb) + 12);                 \
    } while (0)

    // (c, c+4) pair interleave within each 8-k group
    #define V9_STAGE1(dst, v0, v1) do {                                         \
        float2 p;                                                               \
        p.x = v9_tf32((v0).x); p.y = v9_tf32((v1).x); *(float2*)((dst) + 0) = p;\
        p.x = v9_tf32((v0).y); p.y = v9_tf32((v1).y); *(float2*)((dst) + 2) = p;\
        p.x = v9_tf32((v0).z); p.y = v9_tf32((v1).z); *(float2*)((dst) + 4) = p;\
        p.x = v9_tf32((v0).w); p.y = v9_tf32((v1).w); *(float2*)((dst) + 6) = p;\
    } while (0)

    #define V9_STAGE(buf) do {                                                  \
        float* ap = As + ((buf) * 64 + st_row) * V9_ST + st_k16;                \
        V9_STAGE1(ap,     pa[0], pa[1]);                                        \
        V9_STAGE1(ap + 8, pa[2], pa[3]);                                        \
        float* bp = Bs + ((buf) * 64 + st_row) * V9_ST + st_k16;                \
        V9_STAGE1(bp,     pb[0], pb[1]);                                        \
        V9_STAGE1(bp + 8, pb[2], pb[3]);                                        \
    } while (0)

    float d[2][4][4] = {};

    V9_PREFETCH(0);
    V9_STAGE(0);
    V9_PREFETCH(32);

    for (int kt = 0; kt < 24; kt++) {
        const int buf = kt & 1;
        __syncthreads();                       // buf fully staged by all threads
        if (kt < 23) {
            V9_STAGE(buf ^ 1);                 // overlaps with compute below
            if (kt < 22) V9_PREFETCH((kt + 2) * 32);
        }

        const float* Ab = As + buf * 64 * V9_ST;
        const float* Bb = Bs + buf * 64 * V9_ST;
        #pragma unroll
        for (int s = 0; s < 4; s++) {
            unsigned afr[2][4];
            #pragma unroll
            for (int mf = 0; mf < 2; mf++) {
                const int r0 = warpM * 32 + mf * 16 + g;
                float2 p0 = *(const float2*)(Ab + r0 * V9_ST + s * 8 + t * 2);
                float2 p1 = *(const float2*)(Ab + (r0 + 8) * V9_ST + s * 8 + t * 2);
                afr[mf][0] = __float_as_uint(p0.x);
                afr[mf][1] = __float_as_uint(p1.x);
                afr[mf][2] = __float_as_uint(p0.y);
                afr[mf][3] = __float_as_uint(p1.y);
            }
            #pragma unroll
            for (int nf = 0; nf < 4; nf++) {
                const int n = warpN * 32 + nf * 8 + g;
                float2 q = *(const float2*)(Bb + n * V9_ST + s * 8 + t * 2);
                unsigned bfr[2] = { __float_as_uint(q.x), __float_as_uint(q.y) };
                v9_mma(d[0][nf], afr[0], bfr);
                v9_mma(d[1][nf], afr[1], bfr);
            }
        }
    }

    #pragma unroll
    for (int mf = 0; mf < 2; mf++) {
        const int r0 = warpM * 32 + mf * 16 + g;
        #pragma unroll
        for (int nf = 0; nf < 4; nf++) {
            const int c0 = jBase + warpN * 32 + nf * 8 + t * 2;
            float2 bias = make_float2(0.f, 0.f);
            if (isQ) bias = *(const float2*)(b1 + c0);
            float2 v0 = make_float2(d[mf][nf][0] + bias.x, d[mf][nf][1] + bias.y);
            float2 v1 = make_float2(d[mf][nf][2] + bias.x, d[mf][nf][3] + bias.y);
            *(float2*)(Crow + (size_t)r0 * TWO_D + c0)       = v0;
            *(float2*)(Crow + (size_t)(r0 + 8) * TWO_D + c0) = v1;
        }
    }
}

// ---------------------------------------------------------------------------
// Scores partial, packed f32x2 + ALU-pipe relu (identical to passing R7):
//   part[z][q][s] = sum_{j in chunk z} relu(hq[q][j]+hs[s][j]) * w2[j]
// grid = (8, 4, JCHUNKS=8), 256 threads.
// ---------------------------------------------------------------------------
__global__ void v9_scores(const float* __restrict__ W2)
{
    __shared__ __align__(16) float2 Aq2[8][34];
    __shared__ __align__(16) float2 Bs2[8][66];
    __shared__ float2 ws2[8];

    const int tid    = threadIdx.x;
    const int sBase  = blockIdx.x * 64;
    const int qBase  = blockIdx.y * 32;
    const int jcBase = blockIdx.z * JPER;
    const int ty = tid >> 4;
    const int tx = tid & 15;

    const int aq_q  = tid >> 3;
    const int aq_jp = tid & 7;
    const float* hqPtr = v9_hq + (size_t)(qBase + aq_q) * TWO_D + jcBase + aq_jp * 2;
    const int bs_s  = tid >> 2;
    const int bs_jp = (tid & 3) * 2;
    const float* hsPtr = v9_hs + (size_t)(sBase + bs_s) * TWO_D + jcBase + bs_jp * 2;

    double dacc[2][4] = {};
    ull acc2[2][4] = {};

    for (int jt = 0; jt < JPER; jt += 16) {
        float2 aval = *(const float2*)(hqPtr + jt);
        float4 bval = *(const float4*)(hsPtr + jt);
        float2 wval = make_float2(0.f, 0.f);
        if (tid < 8) wval = *(const float2*)(W2 + jcBase + jt + tid * 2);
        __syncthreads();
        Aq2[aq_jp][aq_q] = aval;
        Bs2[bs_jp][bs_s]     = make_float2(bval.x, bval.y);
        Bs2[bs_jp + 1][bs_s] = make_float2(bval.z, bval.w);
        if (tid < 8) ws2[tid] = wval;
        __syncthreads();

        #pragma unroll
        for (int jp = 0; jp < 8; jp++) {
            const ull w2v = *(const ull*)&ws2[jp];
            const ull a0  = *(const ull*)&Aq2[jp][ty * 2];
            const ull a1  = *(const ull*)&Aq2[jp][ty * 2 + 1];
            #pragma unroll
            for (int l = 0; l < 4; l++) {
                const ull bv = *(const ull*)&Bs2[jp][tx + l * 16];
                ull t0; V9_ADD2(t0, a0, bv);
                t0 = v9_relu2(t0);
                V9_FMA2(acc2[0][l], t0, w2v);
                ull t1; V9_ADD2(t1, a1, bv);
                t1 = v9_relu2(t1);
                V9_FMA2(acc2[1][l], t1, w2v);
            }
        }

        if ((jt & 63) == 48) {
            #pragma unroll
            for (int i = 0; i < 2; i++)
                #pragma unroll
                for (int l = 0; l < 4; l++) {
                    unsigned lo, hi;
                    asm("mov.b64 {%0,%1}, %2;" : "=r"(lo), "=r"(hi) : "l"(acc2[i][l]));
                    dacc[i][l] += (double)(__uint_as_float(lo) + __uint_as_float(hi));
                    acc2[i][l] = 0ull;
                }
        }
    }

    double* outp = v9_part + (size_t)blockIdx.z * (Q_N * S_N);
    #pragma unroll
    for (int i = 0; i < 2; i++)
        #pragma unroll
        for (int l = 0; l < 4; l++)
            outp[(size_t)(qBase + ty * 2 + i) * S_N + sBase + tx + l * 16] = dacc[i][l];
}

// ---------------------------------------------------------------------------
// Per-query aggregate + softmax + pred + merged final loss reduction (ticket).
// grid = 128 blocks, 128 threads. All fp64, deterministic.
// ---------------------------------------------------------------------------
__global__ void v9_agg(const int* __restrict__ labels,
                       const int* __restrict__ targets,
                       const float* __restrict__ b2,
                       float* __restrict__ out, int out_size)
{
    __shared__ double sc[S_N];
    __shared__ int    lab[S_N];
    __shared__ double aggv[C_N];
    __shared__ double redv[C_N];
    __shared__ int    redi[C_N];
    __shared__ double rede[C_N];
    __shared__ int    isLast;
    __shared__ double lred[Q_N];

    const int q   = blockIdx.x;
    const int tid = threadIdx.x;
    const double b2v = (double)b2[0];

    for (int s = tid; s < S_N; s += 128) lab[s] = labels[s];

    for (int s = tid; s < S_N; s += 128) {
        double v = 0.0;
        #pragma unroll
        for (int z = 0; z < JCHUNKS; z++)
            v += v9_part[(size_t)z * (Q_N * S_N) + (size_t)q * S_N + s];
        sc[s] = v + b2v;
    }
    __syncthreads();

    if (tid < C_N) {
        double ssum = 0.0;
        int cnt = 0;
        for (int s = 0; s < S_N; s++)
            if (lab[s] == tid) { ssum += sc[s]; cnt++; }
        aggv[tid] = ssum / (double)(cnt > 1 ? cnt : 1);
        redv[tid] = aggv[tid];
        redi[tid] = tid;
    }
    __syncthreads();

    #pragma unroll
    for (int off = C_N / 2; off > 0; off >>= 1) {
        if (tid < off) {
            if (redv[tid + off] > redv[tid] ||
                (redv[tid + off] == redv[tid] && redi[tid + off] < redi[tid])) {
                redv[tid] = redv[tid + off];
                redi[tid] = redi[tid + off];
            }
        }
        __syncthreads();
    }
    const double mx = redv[0];
    const int    am = redi[0];

    if (tid < C_N) rede[tid] = exp(aggv[tid] - mx);
    __syncthreads();
    #pragma unroll
    for (int off = C_N / 2; off > 0; off >>= 1) {
        if (tid < off) rede[tid] += rede[tid + off];
        __syncthreads();
    }

    if (tid == 0) {
        const int tgt = targets[q];
        const double logp = aggv[tgt] - mx - log(rede[0]);
        v9_loss[q] = -logp;
        if (1 + q < out_size) out[1 + q] = (am == tgt) ? 1.0f : 0.0f;
        __threadfence();
        unsigned tk = atomicAdd(&v9_ticket, 1u);
        isLast = (tk == (unsigned)(Q_N - 1));
    }
    __syncthreads();

    if (isLast) {
        __threadfence();
        lred[tid] = v9_loss[tid];
        __syncthreads();
        #pragma unroll
        for (int off = Q_N / 2; off > 0; off >>= 1) {
            if (tid < off) lred[tid] += lred[tid + off];
            __syncthreads();
        }
        if (tid == 0) {
            if (out_size > 0) out[0] = (float)(lred[0] / (double)Q_N);
            v9_ticket = 0;
        }
    }
}

// ---------------------------------------------------------------------------
extern "C" void kernel_launch(void* const* d_in, const int* in_sizes, int n_in,
                              void* d_out, int out_size)
{
    const float* query   = (const float*)d_in[0];
    const float* support = (const float*)d_in[1];
    const float* W1      = (const float*)d_in[2];
    const float* b1      = (const float*)d_in[3];
    const float* W2      = (const float*)d_in[4];
    const float* b2      = (const float*)d_in[5];
    const int*   labels  = (const int*)  d_in[6];
    const int*   targets = (const int*)  d_in[7];
    (void)in_sizes; (void)n_in;

    float* out = (float*)d_out;

    cudaFuncSetAttribute(v9_gemm, cudaFuncAttributeMaxDynamicSharedMemorySize, V9_SMEM);

    v9_gemm  <<<dim3(TWO_D/64, 10), 128, V9_SMEM>>>(query, support, W1, b1);
    v9_scores<<<dim3(S_N/64, Q_N/32, JCHUNKS), 256>>>(W2);
    v9_agg   <<<Q_N, 128>>>(labels, targets, b2, out, out_size);
}